// round 16
// baseline (speedup 1.0000x reference)
#include <cuda_runtime.h>
#include <cuda_fp16.h>
#include <cstdint>
#include <math.h>

#define BB 2
#define SS 2048
#define DD 1024
#define HH 16
#define HW 64
#define MM (BB*SS)   // 4096

// ---------------- scratch (no cudaMalloc allowed) ---------------------------
__device__ __half g_xh[(size_t)MM * DD];                // 8 MB
__device__ __half g_Wh[3][(size_t)DD * DD];             // 6 MB
__device__ __half g_Qh[(size_t)MM * DD];                // 8 MB
__device__ __half g_Kh[(size_t)MM * DD];                // 8 MB
__device__ __half g_Vt[(size_t)MM * DD];                // 8 MB  V transposed per head: [bh][w][s]
__device__ unsigned char g_S8[(size_t)BB * HH * SS * SS]; // 128 MB (e^s, e4m3, permuted)
__device__ float  g_Z [(size_t)BB * HH * SS];           // Z1

// ---------------- PTX helpers (non-arch-specific only) ----------------------
__device__ __forceinline__ void mma_f16(float c[4],
                                        uint32_t a0, uint32_t a1, uint32_t a2, uint32_t a3,
                                        uint32_t b0, uint32_t b1) {
    asm volatile(
        "mma.sync.aligned.m16n8k16.row.col.f32.f16.f16.f32 "
        "{%0,%1,%2,%3}, {%4,%5,%6,%7}, {%8,%9}, {%0,%1,%2,%3};"
        : "+f"(c[0]), "+f"(c[1]), "+f"(c[2]), "+f"(c[3])
        : "r"(a0), "r"(a1), "r"(a2), "r"(a3), "r"(b0), "r"(b1));
}
__device__ __forceinline__ void ldsm_x4(uint32_t& r0, uint32_t& r1,
                                        uint32_t& r2, uint32_t& r3, uint32_t addr) {
    asm volatile("ldmatrix.sync.aligned.m8n8.x4.shared.b16 {%0,%1,%2,%3}, [%4];"
                 : "=r"(r0), "=r"(r1), "=r"(r2), "=r"(r3) : "r"(addr));
}
__device__ __forceinline__ uint32_t smem_u32(const void* p) {
    uint32_t a;
    asm("{ .reg .u64 t; cvta.to.shared.u64 t, %1; cvt.u32.u64 %0, t; }"
        : "=r"(a) : "l"(p));
    return a;
}
__device__ __forceinline__ void cp_async16(uint32_t s, const void* g) {
    asm volatile("cp.async.cg.shared.global [%0], [%1], 16;" :: "r"(s), "l"(g));
}
__device__ __forceinline__ void cp_commit() {
    asm volatile("cp.async.commit_group;" ::: "memory");
}
__device__ __forceinline__ void cp_wait1() {
    asm volatile("cp.async.wait_group 1;" ::: "memory");
}

// ---------------- fp8 converters ---------------------------------------------
__device__ __forceinline__ uint32_t cvt_h2_e4m3(__half2 lo, __half2 hi) {
    unsigned short a, b;
    asm("cvt.rn.satfinite.e4m3x2.f16x2 %0, %1;" : "=h"(a) : "r"(*(uint32_t*)&lo));
    asm("cvt.rn.satfinite.e4m3x2.f16x2 %0, %1;" : "=h"(b) : "r"(*(uint32_t*)&hi));
    return (uint32_t)a | ((uint32_t)b << 16);
}
__device__ __forceinline__ __half2 cvt_e4m3_h2(unsigned short v) {
    uint32_t r;
    asm("cvt.rn.f16x2.e4m3x2 %0, %1;" : "=r"(r) : "h"(v));
    return *(__half2*)&r;
}

// ---------------- half2 exp variants ----------------------------------------
__device__ __forceinline__ __half2 hexp2s(float s0, float s1) {
    const float C8 = 0.18033688f;            // 0.125 * log2(e)
    __half2 y2 = __floats2half2_rn(s0 * C8, s1 * C8);
    y2 = __hmin2(__hmax2(y2, __floats2half2_rn(-14.f, -14.f)),
                 __floats2half2_rn(14.f, 14.f));
    const __half2 magic = __floats2half2_rn(1536.f, 1536.f);
    __half2 z2 = __hadd2(y2, magic);
    __half2 n2 = __hsub2(z2, magic);
    __half2 f2 = __hsub2(y2, n2);
    __half2 p  = __floats2half2_rn(0.00961813f, 0.00961813f);
    p = __hfma2(p, f2, __floats2half2_rn(0.05550411f, 0.05550411f));
    p = __hfma2(p, f2, __floats2half2_rn(0.24022651f, 0.24022651f));
    p = __hfma2(p, f2, __floats2half2_rn(0.69314718f, 0.69314718f));
    p = __hfma2(p, f2, __floats2half2_rn(1.0f, 1.0f));
    uint32_t zb = *(uint32_t*)&z2;
    uint32_t sb = ((zb - 0x65F165F1u) & 0x001F001Fu) << 10;
    return __hmul2(p, *(__half2*)&sb);
}
__device__ __forceinline__ __half2 texp_h2(__half2 e2, __half2 iz2) {
    __half2 p = __hmul2(e2, iz2);
    __half2 r = __floats2half2_rn(4.1666668e-2f, 4.1666668e-2f);
    r = __hfma2(r, p, __floats2half2_rn(1.6666667e-1f, 1.6666667e-1f));
    r = __hfma2(r, p, __floats2half2_rn(0.5f, 0.5f));
    r = __hfma2(r, p, __floats2half2_rn(1.0f, 1.0f));
    r = __hfma2(r, p, __floats2half2_rn(1.0f, 1.0f));
    return r;
}

// ============================================================================
// K0: fp32 -> fp16 convert
// ============================================================================
__global__ void __launch_bounds__(256)
to_half_k(const float* __restrict__ x,  const float* __restrict__ Wq,
          const float* __restrict__ Wk, const float* __restrict__ Wv) {
    const int seg = blockIdx.y;
    const size_t idx = ((size_t)blockIdx.x * 256 + threadIdx.x) * 8;
    const float* src;
    __half* dst;
    if (seg < 4) { src = x + (size_t)seg * 1048576; dst = g_xh + (size_t)seg * 1048576; }
    else if (seg == 4) { src = Wq; dst = g_Wh[0]; }
    else if (seg == 5) { src = Wk; dst = g_Wh[1]; }
    else               { src = Wv; dst = g_Wh[2]; }
    float4 a = *(const float4*)(src + idx);
    float4 b = *(const float4*)(src + idx + 4);
    __half2 h0 = __floats2half2_rn(a.x, a.y);
    __half2 h1 = __floats2half2_rn(a.z, a.w);
    __half2 h2 = __floats2half2_rn(b.x, b.y);
    __half2 h3 = __floats2half2_rn(b.z, b.w);
    uint4 o;
    o.x = *(uint32_t*)&h0; o.y = *(uint32_t*)&h1;
    o.z = *(uint32_t*)&h2; o.w = *(uint32_t*)&h3;
    *(uint4*)(dst + idx) = o;
}

#define HST  72             // fp16 tile row stride in halves
#define HSTB (HST * 2)
#define ESTB 80             // fp8 E tile row stride in bytes

#define LDSM_OFF_A(lane) ((uint32_t)((((lane) & 7) + (((lane) >> 3) & 1) * 8) * HSTB + ((lane) >> 4) * 16))
#define LDSM_OFF_B(lane) ((uint32_t)((((lane) & 7) + ((lane) >> 4) * 8) * HSTB + (((lane) >> 3) & 1) * 16))
#define LDSM_OFF_E(lane) ((uint32_t)((((lane) & 7) + (((lane) >> 3) & 1) * 8) * ESTB + ((lane) >> 4) * 16))

// ============================================================================
// K1: fp16 GEMM, 3-stage cp.async pipeline, ONE barrier per k-tile.
// ============================================================================
__global__ void __launch_bounds__(256, 2)
gemm_h(const float* __restrict__ bq, const float* __restrict__ bk,
       const float* __restrict__ bv) {
    const int which = blockIdx.z;
    const __half* W    = g_Wh[which];
    const float* bias  = (which == 0) ? bq : (which == 1) ? bk : bv;

    extern __shared__ __half hsm[];
    __half* At = hsm;                  // [3][128][HST]
    __half* Bt = hsm + 3 * 128 * HST;  // [3][128][HST]
    const uint32_t aBase = smem_u32(At);
    const uint32_t bBase = smem_u32(Bt);

    const int tid  = threadIdx.x;
    const int wid  = tid >> 5;
    const int lane = tid & 31;
    const int qid  = lane & 3;
    const int m0 = blockIdx.y * 128;
    const int n0 = blockIdx.x * 128;
    const int warp_m = (wid & 1) * 64;
    const int warp_n = (wid >> 1) * 32;
    const int grp  = lane >> 2;

    const uint32_t offA = LDSM_OFF_A(lane);
    const uint32_t offB = LDSM_OFF_B(lane);

    // prologue: issue tiles 0 and 1 (separate groups)
#pragma unroll
    for (int pk = 0; pk < 2; pk++) {
#pragma unroll
        for (int t = 0; t < 4; t++) {
            int idx = tid + t * 256;
            int row = idx >> 3;
            int c8  = idx & 7;
            cp_async16(aBase + (uint32_t)(pk * 128 * HST + row * HST + c8 * 8) * 2,
                       g_xh + (size_t)(m0 + row) * DD + pk * 64 + c8 * 8);
            cp_async16(bBase + (uint32_t)(pk * 128 * HST + row * HST + c8 * 8) * 2,
                       W + (size_t)(n0 + row) * DD + pk * 64 + c8 * 8);
        }
        cp_commit();
    }

    float acc[4][4][4];
#pragma unroll
    for (int mt = 0; mt < 4; mt++)
#pragma unroll
        for (int nt = 0; nt < 4; nt++)
#pragma unroll
            for (int r = 0; r < 4; r++) acc[mt][nt][r] = 0.f;

    for (int kc = 0; kc < 16; kc++) {
        const int buf = kc % 3;
        cp_wait1();
        __syncthreads();
        if (kc + 2 < 16) {
            const int nb = (kc + 2) % 3;
            const int k2 = (kc + 2) * 64;
#pragma unroll
            for (int t = 0; t < 4; t++) {
                int idx = tid + t * 256;
                int row = idx >> 3;
                int c8  = idx & 7;
                cp_async16(aBase + (uint32_t)(nb * 128 * HST + row * HST + c8 * 8) * 2,
                           g_xh + (size_t)(m0 + row) * DD + k2 + c8 * 8);
                cp_async16(bBase + (uint32_t)(nb * 128 * HST + row * HST + c8 * 8) * 2,
                           W + (size_t)(n0 + row) * DD + k2 + c8 * 8);
            }
        }
        cp_commit();

        const uint32_t aT = aBase + buf * 128 * HSTB + warp_m * HSTB + offA;
        const uint32_t bT = bBase + buf * 128 * HSTB + warp_n * HSTB + offB;
#pragma unroll
        for (int ks = 0; ks < 4; ks++) {
            uint32_t af[4][4], bf[4][2];
#pragma unroll
            for (int mt = 0; mt < 4; mt++)
                ldsm_x4(af[mt][0], af[mt][1], af[mt][2], af[mt][3],
                        aT + mt * 16 * HSTB + ks * 32);
#pragma unroll
            for (int ntp = 0; ntp < 2; ntp++)
                ldsm_x4(bf[2*ntp][0], bf[2*ntp][1], bf[2*ntp+1][0], bf[2*ntp+1][1],
                        bT + ntp * 16 * HSTB + ks * 32);
#pragma unroll
            for (int mt = 0; mt < 4; mt++)
#pragma unroll
                for (int nt = 0; nt < 4; nt++)
                    mma_f16(acc[mt][nt], af[mt][0], af[mt][1], af[mt][2], af[mt][3],
                            bf[nt][0], bf[nt][1]);
        }
    }

    if (which < 2) {
        __half* C = (which == 0) ? g_Qh : g_Kh;
#pragma unroll
        for (int mt = 0; mt < 4; mt++) {
#pragma unroll
            for (int nt = 0; nt < 4; nt++) {
                int col = n0 + warp_n + nt * 8 + 2 * qid;
                float bx = bias[col], by = bias[col + 1];
                int r0 = m0 + warp_m + mt * 16 + grp;
                __half2 o0 = __floats2half2_rn(acc[mt][nt][0] + bx, acc[mt][nt][1] + by);
                __half2 o1 = __floats2half2_rn(acc[mt][nt][2] + bx, acc[mt][nt][3] + by);
                *(__half2*)(C + (size_t)r0 * DD + col) = o0;
                *(__half2*)(C + (size_t)(r0 + 8) * DD + col) = o1;
            }
        }
    } else {
#pragma unroll
        for (int mt = 0; mt < 4; mt++) {
#pragma unroll
            for (int nt = 0; nt < 4; nt++) {
                int col = n0 + warp_n + nt * 8 + 2 * qid;
                float bx = bias[col], by = bias[col + 1];
                int r0 = m0 + warp_m + mt * 16 + grp;
                int hh = col >> 6, w = col & 63;
                int b1 = r0 >> 11, s1 = r0 & 2047;
                size_t base = ((size_t)(b1 * 16 + hh) * 64);
                g_Vt[(base + w    ) * SS + s1]     = __float2half(acc[mt][nt][0] + bx);
                g_Vt[(base + w + 1) * SS + s1]     = __float2half(acc[mt][nt][1] + by);
                g_Vt[(base + w    ) * SS + s1 + 8] = __float2half(acc[mt][nt][2] + bx);
                g_Vt[(base + w + 1) * SS + s1 + 8] = __float2half(acc[mt][nt][3] + by);
            }
        }
    }
}

// ============================================================================
// K2: scores, 3-stage pipeline, one barrier per n-tile. e (e4m3) -> g_S8.
// ============================================================================
__global__ void __launch_bounds__(256, 2)
attn_scores_h() {
    extern __shared__ __half hsm2[];
    __half* Qs = hsm2;                  // [128][HST]
    __half* Kt = hsm2 + 128 * HST;      // [3][128][HST]
    __shared__ float sz[4][128];
    const uint32_t qBase = smem_u32(Qs);
    const uint32_t kBase = smem_u32(Kt);

    const int bh = blockIdx.y;
    const int b  = bh >> 4, h = bh & 15;
    const int q0 = blockIdx.x * 128;
    const int tid  = threadIdx.x;
    const int wid  = tid >> 5;
    const int lane = tid & 31;
    const int grp  = lane >> 2;
    const int qid  = lane & 3;
    const int widm = wid & 1, widn = wid >> 1;
    const int warp_m = widm * 64, warp_n = widn * 32;
    unsigned char* Sm8 = g_S8 + (size_t)bh * SS * SS;

    const uint32_t offA = LDSM_OFF_A(lane);
    const uint32_t offB = LDSM_OFF_B(lane);

    // prologue: K tiles 0,1
#pragma unroll
    for (int pk = 0; pk < 2; pk++) {
#pragma unroll
        for (int t = 0; t < 4; t++) {
            int idx = tid + t * 256;
            int row = idx >> 3;
            int c8  = idx & 7;
            cp_async16(kBase + (uint32_t)(pk * 128 * HST + row * HST + c8 * 8) * 2,
                       g_Kh + (size_t)(b*SS + pk * 128 + row) * DD + h*HW + c8*8);
        }
        cp_commit();
    }

    // Q resident
#pragma unroll
    for (int t = 0; t < 4; t++) {
        int idx = tid + t * 256;
        int row = idx >> 3;
        int c8  = idx & 7;
        uint4 v = *(const uint4*)(g_Qh + (size_t)(b*SS + q0 + row) * DD + h*HW + c8*8);
        *(uint4*)(Qs + row * HST + c8 * 8) = v;
    }

    float zlo[4] = {0.f,0.f,0.f,0.f}, zhi[4] = {0.f,0.f,0.f,0.f};

    for (int it = 0; it < 16; it++) {
        const int buf = it % 3;
        cp_wait1();
        __syncthreads();
        if (it + 2 < 16) {
            const int nb = (it + 2) % 3;
            const int n2 = (it + 2) * 128;
#pragma unroll
            for (int t = 0; t < 4; t++) {
                int idx = tid + t * 256;
                int row = idx >> 3;
                int c8  = idx & 7;
                cp_async16(kBase + (uint32_t)(nb * 128 * HST + row * HST + c8 * 8) * 2,
                           g_Kh + (size_t)(b*SS + n2 + row) * DD + h*HW + c8*8);
            }
        }
        cp_commit();

        float acc[4][4][4];
#pragma unroll
        for (int mt = 0; mt < 4; mt++)
#pragma unroll
            for (int nt = 0; nt < 4; nt++)
#pragma unroll
                for (int r = 0; r < 4; r++) acc[mt][nt][r] = 0.f;

        const uint32_t qT = qBase + warp_m * HSTB + offA;
        const uint32_t kT = kBase + buf * 128 * HSTB + warp_n * HSTB + offB;
#pragma unroll
        for (int ks = 0; ks < 4; ks++) {
            uint32_t af[4][4], bf[4][2];
#pragma unroll
            for (int mt = 0; mt < 4; mt++)
                ldsm_x4(af[mt][0], af[mt][1], af[mt][2], af[mt][3],
                        qT + mt * 16 * HSTB + ks * 32);
#pragma unroll
            for (int ntp = 0; ntp < 2; ntp++)
                ldsm_x4(bf[2*ntp][0], bf[2*ntp][1], bf[2*ntp+1][0], bf[2*ntp+1][1],
                        kT + ntp * 16 * HSTB + ks * 32);
#pragma unroll
            for (int mt = 0; mt < 4; mt++)
#pragma unroll
                for (int nt = 0; nt < 4; nt++)
                    mma_f16(acc[mt][nt], af[mt][0], af[mt][1], af[mt][2], af[mt][3],
                            bf[nt][0], bf[nt][1]);
        }

        const int n0 = it * 128;
#pragma unroll
        for (int mt = 0; mt < 4; mt++) {
            int r1 = warp_m + mt * 16 + grp;
            int r2 = r1 + 8;
#pragma unroll
            for (int ntp = 0; ntp < 2; ntp++) {
                const float* aE = acc[mt][2*ntp];
                const float* aO = acc[mt][2*ntp+1];
                __half2 hAe = hexp2s(aE[0], aE[1]);
                __half2 hAo = hexp2s(aO[0], aO[1]);
                __half2 hBe = hexp2s(aE[2], aE[3]);
                __half2 hBo = hexp2s(aO[2], aO[3]);
                float2 f;
                f = __half22float2(__hadd2(hAe, hAo)); zlo[mt] += f.x + f.y;
                f = __half22float2(__hadd2(hBe, hBo)); zhi[mt] += f.x + f.y;
                uint32_t wA = cvt_h2_e4m3(hAe, hAo);
                uint32_t wB = cvt_h2_e4m3(hBe, hBo);
                int off = n0 + warp_n + ntp * 16 + 4 * qid;
                *(uint32_t*)(Sm8 + (size_t)(q0 + r1) * SS + off) = wA;
                *(uint32_t*)(Sm8 + (size_t)(q0 + r2) * SS + off) = wB;
            }
        }
    }

#pragma unroll
    for (int o = 1; o <= 2; o <<= 1)
#pragma unroll
        for (int mt = 0; mt < 4; mt++) {
            zlo[mt] += __shfl_xor_sync(0xffffffffu, zlo[mt], o);
            zhi[mt] += __shfl_xor_sync(0xffffffffu, zhi[mt], o);
        }
    if (qid == 0) {
#pragma unroll
        for (int mt = 0; mt < 4; mt++) {
            sz[widn][warp_m + mt * 16 + grp]     = zlo[mt];
            sz[widn][warp_m + mt * 16 + grp + 8] = zhi[mt];
        }
    }
    __syncthreads();
    if (tid < 128) {
        float z = (sz[0][tid] + sz[1][tid]) + (sz[2][tid] + sz[3][tid]);
        g_Z[(size_t)bh * SS + q0 + tid] = z;
    }
}

// ============================================================================
// K3: PV, 3-stage pipeline, one barrier per k-tile. fp8 E, fp16 V.
// ============================================================================
__global__ void __launch_bounds__(256, 2)
attn_pv_h(float* __restrict__ out) {
    extern __shared__ __half hsm3[];
    unsigned char* Et = (unsigned char*)hsm3;          // [3][128][ESTB]
    __half* Vt = (__half*)(Et + 3 * 128 * ESTB);       // [3][64][HST]
    const uint32_t eBase = smem_u32(Et);
    const uint32_t vBase = smem_u32(Vt);

    const int bh = blockIdx.y;
    const int b  = bh >> 4, h = bh & 15;
    const int q0 = blockIdx.x * 128;
    const int tid  = threadIdx.x;
    const int wid  = tid >> 5;
    const int lane = tid & 31;
    const int grp  = lane >> 2;
    const int qid  = lane & 3;
    const unsigned char* Sm8 = g_S8 + (size_t)bh * SS * SS;
    const __half* Vg = g_Vt + (size_t)bh * 64 * SS;

    const int rA = wid * 16 + grp;
    const int rB = rA + 8;
    const float invZa = 1.0f / g_Z[(size_t)bh * SS + q0 + rA];
    const float invZb = 1.0f / g_Z[(size_t)bh * SS + q0 + rB];
    const __half2 izA = __half2half2(__float2half(invZa));
    const __half2 izB = __half2half2(__float2half(invZb));

    const uint32_t offE = LDSM_OFF_E(lane);
    const uint32_t offB = LDSM_OFF_B(lane);

    // prologue: tiles 0,1
#pragma unroll
    for (int pk = 0; pk < 2; pk++) {
#pragma unroll
        for (int t = 0; t < 2; t++) {
            int idx = tid + t * 256;
            int er = idx >> 2, ec = idx & 3;
            cp_async16(eBase + (uint32_t)(pk * 128 * ESTB + er * ESTB + ec * 16),
                       Sm8 + (size_t)(q0 + er) * SS + pk * 64 + ec * 16);
        }
#pragma unroll
        for (int t = 0; t < 2; t++) {
            int idx = tid + t * 256;
            int vr = idx >> 3, vc = idx & 7;
            cp_async16(vBase + (uint32_t)(pk * 64 * HST + vr * HST + vc * 8) * 2,
                       Vg + (size_t)vr * SS + pk * 64 + vc * 8);
        }
        cp_commit();
    }

    float accPV[8][4];
#pragma unroll
    for (int nt = 0; nt < 8; nt++)
#pragma unroll
        for (int r = 0; r < 4; r++) accPV[nt][r] = 0.f;
    float z2a = 0.f, z2b = 0.f;

    for (int it = 0; it < 32; it++) {
        const int buf = it % 3;
        cp_wait1();
        __syncthreads();
        if (it + 2 < 32) {
            const int nb = (it + 2) % 3;
            const int k2 = (it + 2) * 64;
#pragma unroll
            for (int t = 0; t < 2; t++) {
                int idx = tid + t * 256;
                int er = idx >> 2, ec = idx & 3;
                cp_async16(eBase + (uint32_t)(nb * 128 * ESTB + er * ESTB + ec * 16),
                           Sm8 + (size_t)(q0 + er) * SS + k2 + ec * 16);
            }
#pragma unroll
            for (int t = 0; t < 2; t++) {
                int idx = tid + t * 256;
                int vr = idx >> 3, vc = idx & 7;
                cp_async16(vBase + (uint32_t)(nb * 64 * HST + vr * HST + vc * 8) * 2,
                           Vg + (size_t)vr * SS + k2 + vc * 8);
            }
        }
        cp_commit();

        const uint32_t eT = eBase + buf * 128 * ESTB + wid * 16 * ESTB + offE;
        const uint32_t vT = vBase + buf * 64 * HSTB + offB;

#pragma unroll
        for (int kp = 0; kp < 2; kp++) {
            uint32_t e0, e1, e2, e3;
            ldsm_x4(e0, e1, e2, e3, eT + kp * 32);
#pragma unroll
            for (int j = 0; j < 2; j++) {
                uint32_t ra = (j == 0) ? e0 : e2;
                uint32_t rb = (j == 0) ? e1 : e3;
                __half2 tA0 = texp_h2(cvt_e4m3_h2((unsigned short)(ra & 0xFFFF)), izA);
                __half2 tA1 = texp_h2(cvt_e4m3_h2((unsigned short)(ra >> 16)),    izA);
                __half2 tB0 = texp_h2(cvt_e4m3_h2((unsigned short)(rb & 0xFFFF)), izB);
                __half2 tB1 = texp_h2(cvt_e4m3_h2((unsigned short)(rb >> 16)),    izB);
                float2 za = __half22float2(__hadd2(tA0, tA1));
                float2 zb = __half22float2(__hadd2(tB0, tB1));
                z2a += za.x + za.y;
                z2b += zb.x + zb.y;
                uint32_t a0 = *(uint32_t*)&tA0, a1 = *(uint32_t*)&tB0;
                uint32_t a2 = *(uint32_t*)&tA1, a3 = *(uint32_t*)&tB1;

                const int ks = kp * 2 + j;
                uint32_t bf[8][2];
#pragma unroll
                for (int ntp = 0; ntp < 4; ntp++)
                    ldsm_x4(bf[2*ntp][0], bf[2*ntp][1], bf[2*ntp+1][0], bf[2*ntp+1][1],
                            vT + ntp * 16 * HSTB + ks * 32);
#pragma unroll
                for (int nt = 0; nt < 8; nt++)
                    mma_f16(accPV[nt], a0, a1, a2, a3, bf[nt][0], bf[nt][1]);
            }
        }
    }

#pragma unroll
    for (int o = 1; o <= 2; o <<= 1) {
        z2a += __shfl_xor_sync(0xffffffffu, z2a, o);
        z2b += __shfl_xor_sync(0xffffffffu, z2b, o);
    }
    const float ra = 1.0f / z2a;
    const float rb = 1.0f / z2b;

#pragma unroll
    for (int nt = 0; nt < 8; nt++) {
        int col = h * HW + nt * 8 + 2 * qid;
        *(float2*)(out + (size_t)(b*SS + q0 + rA) * DD + col) =
            make_float2(accPV[nt][0] * ra, accPV[nt][1] * ra);
        *(float2*)(out + (size_t)(b*SS + q0 + rB) * DD + col) =
            make_float2(accPV[nt][2] * rb, accPV[nt][3] * rb);
    }
}

// ---------------- launch -----------------------------------------------------
extern "C" void kernel_launch(void* const* d_in, const int* in_sizes, int n_in,
                              void* d_out, int out_size) {
    const float* x  = (const float*)d_in[0];
    const float* Wq = (const float*)d_in[1];
    const float* bq = (const float*)d_in[2];
    const float* Wk = (const float*)d_in[3];
    const float* bk = (const float*)d_in[4];
    const float* Wv = (const float*)d_in[5];
    const float* bv = (const float*)d_in[6];
    float* out = (float*)d_out;

    const int smem_gemm = 6 * 128 * HST * sizeof(__half);                 // 110592
    const int smem_sc   = 4 * 128 * HST * sizeof(__half);                 // 73728
    const int smem_pv   = 3 * 128 * ESTB + 3 * 64 * HST * sizeof(__half); // 58368
    cudaFuncSetAttribute(gemm_h,
                         cudaFuncAttributeMaxDynamicSharedMemorySize, smem_gemm);
    cudaFuncSetAttribute(attn_scores_h,
                         cudaFuncAttributeMaxDynamicSharedMemorySize, smem_sc);
    cudaFuncSetAttribute(attn_pv_h,
                         cudaFuncAttributeMaxDynamicSharedMemorySize, smem_pv);

    to_half_k<<<dim3(512, 7), 256>>>(x, Wq, Wk, Wv);

    dim3 gproj(DD / 128, MM / 128, 3);          // (8, 32, 3)
    gemm_h<<<gproj, 256, smem_gemm>>>(bq, bk, bv);

    dim3 gs(SS / 128, BB * HH);                 // (16, 32)
    attn_scores_h<<<gs, 256, smem_sc>>>();
    attn_pv_h<<<gs, 256, smem_pv>>>(out);
}